// round 9
// baseline (speedup 1.0000x reference)
#include <cuda_runtime.h>
#include <cuda_bf16.h>
#include <float.h>
#include <stdint.h>

#define G_N 8
#define T_N 4096
#define H_N 1024
#define E_N 32
#define C_N 64
#define ROWS (G_N*T_N)                      // 32768
#define BR 64                               // rows per gemm block
#define GEMM_BLOCKS (ROWS/BR)               // 512
static const size_t NTOT = (size_t)G_N*T_N*E_N*C_N;   // 67108864

// zero-fill split: gemm covers [0, 416MiB), topk covers [416MiB, 512MiB)
#define ZB_BYTES 32768                      // gemm bulk chunk
#define GZ_CHUNKS 26                        // per gemm block
#define TZB_BYTES 16384                     // topk bulk chunk
#define TZ_CHUNKS 24                        // per topk block
static const size_t TZ_BASE = (size_t)GEMM_BLOCKS * GZ_CHUNKS * ZB_BYTES; // 416MiB

// ---------------- scratch (no allocs allowed) ----------------
__device__ float g_probsT[E_N*ROWS];        // 4 MB: probs transposed [g][e][t]
__device__ float g_zpart[GEMM_BLOCKS];
__device__ int   g_sync;

// ---------------- packed fp32x2 helpers (asm: immune to fast-math) -----------
__device__ __forceinline__ unsigned long long ffma2(unsigned long long a,
                                                    unsigned long long b,
                                                    unsigned long long c) {
    unsigned long long d;
    asm("fma.rn.f32x2 %0, %1, %2, %3;" : "=l"(d) : "l"(a), "l"(b), "l"(c));
    return d;
}
__device__ __forceinline__ unsigned long long fadd2(unsigned long long a,
                                                    unsigned long long b) {
    unsigned long long d;
    asm("add.rn.f32x2 %0, %1, %2;" : "=l"(d) : "l"(a), "l"(b));
    return d;
}
__device__ __forceinline__ unsigned long long fneg2(unsigned long long a) {
    return a ^ 0x8000000080000000ull;
}
__device__ __forceinline__ unsigned long long splat2(float x) {
    unsigned long long d; unsigned int xi = __float_as_uint(x);
    asm("mov.b64 %0, {%1, %1};" : "=l"(d) : "r"(xi));
    return d;
}
__device__ __forceinline__ uint32_t smem_u32(const void* p) {
    uint32_t a;
    asm("{ .reg .u64 t; cvta.to.shared.u64 t, %1; cvt.u32.u64 %0, t; }"
        : "=r"(a) : "l"(p));
    return a;
}

// Accurate expf (<1 ulp) built from __fmaf_rn only (fast-math-proof).
__device__ __forceinline__ float exp_rn(float x) {
    float t = __fmaf_rn(x, 1.4426950408889634f, 12582912.0f);
    float n = __fadd_rn(t, -12582912.0f);
    float f = __fmaf_rn(n, -0.693359375f, x);
    f = __fmaf_rn(n, 2.1219444005469058e-4f, f);
    float p = 1.9841269841e-4f;
    p = __fmaf_rn(p, f, 1.3888888889e-3f);
    p = __fmaf_rn(p, f, 8.3333333333e-3f);
    p = __fmaf_rn(p, f, 4.1666666667e-2f);
    p = __fmaf_rn(p, f, 1.6666666667e-1f);
    p = __fmaf_rn(p, f, 0.5f);
    p = __fmaf_rn(p, f, 1.0f);
    p = __fmaf_rn(p, f, 1.0f);
    int ei = (int)n;
    float sc = __int_as_float((ei + 127) << 23);
    return p * sc;
}

// ---------------- GEMM + softmax + z-loss + partial TMA zeroing --------------
#define KT 32
#define XS 36   // shx row stride (pad): conflict-free broadcast reads
__global__ __launch_bounds__(128) void gemm_softmax_kernel(
    const float* __restrict__ x, const float* __restrict__ W,
    const float* __restrict__ bias, char* __restrict__ zout)
{
    __shared__ __align__(16) float shx[BR * XS];        // 9.2 KB
    __shared__ __align__(16) float shw[KT * E_N];       // 4 KB
    __shared__ __align__(16) float4 zbuf[ZB_BYTES/16];  // 32 KB of zeros
    __shared__ float shz[4];

    int tid  = threadIdx.x;
    int row0 = blockIdx.x * BR;
    int eq   = tid & 3;
    int rg   = tid >> 2;        // 0..31
    int e0   = eq * 8;

    if (blockIdx.x == 0 && tid == 0) g_sync = 0;   // reset topk barrier

    // zero the TMA source buffer (16 float4 per thread)
    const float4 zf4 = make_float4(0.f, 0.f, 0.f, 0.f);
    #pragma unroll
    for (int i = 0; i < 16; i++) zbuf[i * 128 + tid] = zf4;

    unsigned long long ksum[2][4], kcmp[2][4];
    #pragma unroll
    for (int r = 0; r < 2; r++)
        #pragma unroll
        for (int j = 0; j < 4; j++) { ksum[r][j] = 0ull; kcmp[r][j] = 0ull; }

    // prefetch registers
    float4 px[4], pw[2];
    #pragma unroll
    for (int i = 0; i < 4; i++) {
        int j = i * 128 + tid;
        px[i] = *(const float4*)(x + (size_t)(row0 + (j >> 3)) * H_N + (j & 7) * 4);
    }
    #pragma unroll
    for (int i = 0; i < 2; i++) {
        int j = i * 128 + tid;
        pw[i] = *(const float4*)(W + (size_t)(j >> 3) * E_N + (j & 7) * 4);
    }

    uint32_t zb_s = smem_u32(zbuf);

    for (int kt = 0; kt < H_N; kt += KT) {
        #pragma unroll
        for (int i = 0; i < 4; i++) {
            int j = i * 128 + tid;
            *(float4*)&shx[(j >> 3) * XS + (j & 7) * 4] = px[i];
        }
        #pragma unroll
        for (int i = 0; i < 2; i++) {
            int j = i * 128 + tid;
            *(float4*)&shw[(j >> 3) * E_N + (j & 7) * 4] = pw[i];
        }
        __syncthreads();   // also publishes zbuf zeros (iter 0)

        // one 32KB async bulk zero-store per chunk slot (first 26 of 32)
        if (tid == 0 && (kt >> 5) < GZ_CHUNKS) {
            if (kt == 0)
                asm volatile("fence.proxy.async.shared::cta;" ::: "memory");
            char* dst = zout + ((size_t)blockIdx.x * GZ_CHUNKS + (size_t)(kt >> 5)) * ZB_BYTES;
            asm volatile(
                "cp.async.bulk.global.shared::cta.bulk_group [%0], [%1], %2;"
                :: "l"(dst), "r"(zb_s), "r"((unsigned)ZB_BYTES) : "memory");
        }

        int ktn = (kt + KT < H_N) ? kt + KT : 0;
        #pragma unroll
        for (int i = 0; i < 4; i++) {
            int j = i * 128 + tid;
            px[i] = *(const float4*)(x + (size_t)(row0 + (j >> 3)) * H_N + ktn + (j & 7) * 4);
        }
        #pragma unroll
        for (int i = 0; i < 2; i++) {
            int j = i * 128 + tid;
            pw[i] = *(const float4*)(W + (size_t)(ktn + (j >> 3)) * E_N + (j & 7) * 4);
        }

        unsigned long long a[2][4];
        #pragma unroll
        for (int r = 0; r < 2; r++)
            #pragma unroll
            for (int j = 0; j < 4; j++) a[r][j] = 0ull;

        #pragma unroll 8
        for (int kk = 0; kk < KT; kk++) {
            unsigned long long x0 = splat2(shx[rg * XS + kk]);
            unsigned long long x1 = splat2(shx[(rg + 32) * XS + kk]);
            ulonglong2 w0 = *(const ulonglong2*)&shw[kk * E_N + e0];
            ulonglong2 w1 = *(const ulonglong2*)&shw[kk * E_N + e0 + 4];
            a[0][0] = ffma2(x0, w0.x, a[0][0]);
            a[0][1] = ffma2(x0, w0.y, a[0][1]);
            a[0][2] = ffma2(x0, w1.x, a[0][2]);
            a[0][3] = ffma2(x0, w1.y, a[0][3]);
            a[1][0] = ffma2(x1, w0.x, a[1][0]);
            a[1][1] = ffma2(x1, w0.y, a[1][1]);
            a[1][2] = ffma2(x1, w1.x, a[1][2]);
            a[1][3] = ffma2(x1, w1.y, a[1][3]);
        }
        #pragma unroll
        for (int r = 0; r < 2; r++)
            #pragma unroll
            for (int j = 0; j < 4; j++) {
                unsigned long long y = fadd2(a[r][j], fneg2(kcmp[r][j]));
                unsigned long long t = fadd2(ksum[r][j], y);
                kcmp[r][j] = fadd2(fadd2(t, fneg2(ksum[r][j])), fneg2(y));
                ksum[r][j] = t;
            }
        __syncthreads();
    }

    // epilogue: per row -> logits, softmax, transposed store, z partial
    float zacc = 0.0f;
    float bv[8];
    #pragma unroll
    for (int e = 0; e < 8; e++) bv[e] = bias[e0 + e];

    #pragma unroll
    for (int r = 0; r < 2; r++) {
        float l[8];
        #pragma unroll
        for (int j = 0; j < 4; j++) {
            unsigned long long v = fadd2(ksum[r][j], kcmp[r][j]);
            l[2*j]   = __uint_as_float((unsigned int)(v & 0xffffffffull));
            l[2*j+1] = __uint_as_float((unsigned int)(v >> 32));
        }
        #pragma unroll
        for (int e = 0; e < 8; e++) l[e] = __fadd_rn(l[e], bv[e]);

        float m = l[0];
        #pragma unroll
        for (int e = 1; e < 8; e++) m = fmaxf(m, l[e]);
        m = fmaxf(m, __shfl_xor_sync(0xffffffffu, m, 1));
        m = fmaxf(m, __shfl_xor_sync(0xffffffffu, m, 2));

        float p[8], s = 0.f;
        #pragma unroll
        for (int e = 0; e < 8; e++) { p[e] = exp_rn(__fadd_rn(l[e], -m)); s = __fadd_rn(s, p[e]); }
        s = __fadd_rn(s, __shfl_xor_sync(0xffffffffu, s, 1));
        s = __fadd_rn(s, __shfl_xor_sync(0xffffffffu, s, 2));

        int grow = row0 + rg + 32 * r;
        int g    = grow >> 12;
        int t    = grow & (T_N - 1);
        float* dst = g_probsT + ((size_t)g * E_N + e0) * T_N + t;
        #pragma unroll
        for (int e = 0; e < 8; e++)
            dst[(size_t)e * T_N] = __fdiv_rn(p[e], s);   // IEEE div

        float lz = m + logf(s);
        zacc = __fmaf_rn(lz, lz, zacc);
    }

    float v = (eq == 0) ? zacc : 0.0f;
    #pragma unroll
    for (int off = 16; off; off >>= 1)
        v += __shfl_xor_sync(0xffffffffu, v, off);
    if ((tid & 31) == 0) shz[tid >> 5] = v;
    __syncthreads();
    if (tid == 0) {
        float zs = 0.f;
        #pragma unroll
        for (int w = 0; w < 4; w++) zs += shz[w];
        g_zpart[blockIdx.x] = zs;
        asm volatile("cp.async.bulk.commit_group;" ::: "memory");
        asm volatile("cp.async.bulk.wait_group 0;" ::: "memory");
    }
}

// ------- per-(g,e) exact top-64 radix select + zero slice + fused scatter ----
// Issues its 96MB/256 slice of zero-fill up front (drains under select
// compute); device-counter barrier (all 256 blocks co-resident) orders ALL
// zeros before ANY winner store. Selection semantics = jax.lax.top_k.
__global__ __launch_bounds__(256) void topk_kernel(float* __restrict__ out)
{
    __shared__ unsigned int ub[T_N];               // 16 KB
    __shared__ __align__(16) float4 zbuf[TZB_BYTES/16];  // 16 KB zeros
    __shared__ int hist[256];
    __shared__ int wtot[8], wext[8];
    __shared__ int sel_bin, sel_krem;
    __shared__ unsigned long long glist[C_N];
    __shared__ int gcnt;
    __shared__ float red[8];

    int bid  = blockIdx.x;           // 0..255 = g*32 + e
    int g    = bid >> 5;
    int e    = bid & 31;
    int tid  = threadIdx.x;
    int lane = tid & 31;
    int wid  = tid >> 5;

    // zero TMA source buffer (4 float4 per thread)
    const float4 zf4 = make_float4(0.f, 0.f, 0.f, 0.f);
    #pragma unroll
    for (int i = 0; i < 4; i++) zbuf[i * 256 + tid] = zf4;

    // load prob bits (order-preserving for positive floats)
    const float4* base = (const float4*)(g_probsT + (size_t)bid * T_N);
    #pragma unroll
    for (int i = 0; i < 4; i++) {
        float4 v = base[tid * 4 + i];
        uint4 u;
        u.x = __float_as_uint(v.x); u.y = __float_as_uint(v.y);
        u.z = __float_as_uint(v.z); u.w = __float_as_uint(v.w);
        *(uint4*)&ub[tid * 16 + i * 4] = u;
    }
    if (tid == 0) gcnt = 0;
    __syncthreads();

    // issue this block's zero slice (async; drains under select compute)
    if (tid == 0) {
        asm volatile("fence.proxy.async.shared::cta;" ::: "memory");
        uint32_t zs = smem_u32(zbuf);
        char* zb = (char*)out + TZ_BASE + (size_t)bid * TZ_CHUNKS * TZB_BYTES;
        #pragma unroll
        for (int i = 0; i < TZ_CHUNKS; i++)
            asm volatile(
                "cp.async.bulk.global.shared::cta.bulk_group [%0], [%1], %2;"
                :: "l"(zb + (size_t)i * TZB_BYTES), "r"(zs),
                   "r"((unsigned)TZB_BYTES) : "memory");
    }

    // ---- 4-level radix select (shuffle-based suffix scans) ----
    unsigned int pref = 0;
    int k_rem = C_N;
    for (int lvl = 0; lvl < 4; lvl++) {
        int sh = 24 - 8 * lvl;
        hist[tid] = 0;
        __syncthreads();
        #pragma unroll
        for (int i = 0; i < 16; i++) {
            unsigned int b = ub[tid * 16 + i];
            bool cand = (lvl == 0) || ((b >> (32 - 8 * lvl)) == pref);
            if (cand) atomicAdd(&hist[(b >> sh) & 255], 1);
        }
        __syncthreads();
        // block suffix-inclusive scan of hist via warp shfl + 8-warp combine
        int v = hist[tid];
        #pragma unroll
        for (int off = 1; off < 32; off <<= 1) {
            int t = __shfl_down_sync(0xffffffffu, v, off);
            if (lane + off < 32) v += t;
        }
        if (lane == 0) wtot[wid] = v;           // warp total (suffix at lane 0)
        __syncthreads();
        if (tid < 8) {
            int s = 0;
            for (int w = tid + 1; w < 8; w++) s += wtot[w];
            wext[tid] = s;                       // exclusive suffix of warp totals
        }
        __syncthreads();
        // recompute local suffix (v was consumed): redo cheaply
        int vl = hist[tid];
        #pragma unroll
        for (int off = 1; off < 32; off <<= 1) {
            int t = __shfl_down_sync(0xffffffffu, vl, off);
            if (lane + off < 32) vl += t;
        }
        int S = vl + wext[wid];                  // sum over all bins >= tid
        __syncthreads();
        hist[tid] = S;
        __syncthreads();
        int nxt = (tid < 255) ? hist[tid + 1] : 0;
        if (S >= k_rem && nxt < k_rem) { sel_bin = tid; sel_krem = k_rem - nxt; }
        __syncthreads();
        pref  = (pref << 8) | (unsigned int)sel_bin;
        k_rem = sel_krem;
        __syncthreads();
    }
    unsigned int thr = pref;         // exact 64th-largest bit pattern
    int need   = k_rem;              // # equals to take (smallest indices)
    int cnt_gt = C_N - need;

    // compact strictly-greater winners (unordered) into smem
    #pragma unroll
    for (int i = 0; i < 16; i++) {
        int t = tid * 16 + i;
        unsigned int b = ub[t];
        if (b > thr) {
            int p = atomicAdd(&gcnt, 1);
            glist[p] = ((unsigned long long)b << 32) |
                       (unsigned long long)(0xFFFFFFFFu - (unsigned int)t);
        }
    }

    // equals: block prefix scan (ascending t) via warp shfl + combine
    int leq = 0;
    #pragma unroll
    for (int i = 0; i < 16; i++) leq += (ub[tid * 16 + i] == thr);
    int pv = leq;
    #pragma unroll
    for (int off = 1; off < 32; off <<= 1) {
        int t = __shfl_up_sync(0xffffffffu, pv, off);
        if (lane >= off) pv += t;
    }
    if (lane == 31) wtot[wid] = pv;
    __syncthreads();
    if (tid < 8) {
        int s = 0;
        for (int w = 0; w < tid; w++) s += wtot[w];
        wext[tid] = s;
    }
    __syncthreads();
    int ir0 = pv - leq + wext[wid];   // exclusive prefix of equal-counts
    __syncthreads();                  // glist/gcnt final

    // ---- global barrier: all zero slices must land before winner stores ----
    if (tid == 0) {
        asm volatile("cp.async.bulk.commit_group;" ::: "memory");
        asm volatile("cp.async.bulk.wait_group 0;" ::: "memory");
        __threadfence();
        atomicAdd(&g_sync, 1);
        volatile int* sy = &g_sync;
        while (*sy < 256) __nanosleep(64);
    }
    __syncthreads();

    // ---- winner stores (combine + dispatch) ----
    const size_t ge_off = ((size_t)g * T_N) * (E_N * C_N) + (size_t)e * C_N;

    {   // equals at threshold: ranks cnt_gt + index-rank
        int ir = ir0;
        #pragma unroll
        for (int i = 0; i < 16; i++) {
            int t = tid * 16 + i;
            if (ub[t] == thr) {
                if (ir < need) {
                    size_t off = ge_off + (size_t)t * (E_N * C_N) + (cnt_gt + ir);
                    out[off]        = __uint_as_float(thr);
                    out[NTOT + off] = 1.0f;
                }
                ir++;
            }
        }
    }
    if (tid < cnt_gt) {   // strictly greater: rank by composite key
        unsigned long long mk = glist[tid];
        int rank = 0;
        for (int j = 0; j < cnt_gt; j++) rank += (glist[j] > mk);
        int t = (int)(0xFFFFFFFFu - (unsigned int)(mk & 0xFFFFFFFFull));
        size_t off = ge_off + (size_t)t * (E_N * C_N) + rank;
        out[off]        = __uint_as_float((unsigned int)(mk >> 32));
        out[NTOT + off] = 1.0f;
    }

    // z-loss (block 0; slot not covered by any zero region)
    if (bid == 0) {
        float v = 0.0f;
        for (int j = tid; j < GEMM_BLOCKS; j += 256) v += g_zpart[j];
        #pragma unroll
        for (int off = 16; off; off >>= 1)
            v += __shfl_xor_sync(0xffffffffu, v, off);
        if ((tid & 31) == 0) red[tid >> 5] = v;
        __syncthreads();
        if (tid == 0) {
            float zs = 0.f;
            #pragma unroll
            for (int w = 0; w < 8; w++) zs += red[w];
            out[2 * NTOT] = zs * (1.0f / (float)(G_N * T_N));
        }
    }
}

// ---------------- launch ----------------
extern "C" void kernel_launch(void* const* d_in, const int* in_sizes, int n_in,
                              void* d_out, int out_size)
{
    const float* x = (const float*)d_in[0];   // [G,T,H] fp32
    const float* W = (const float*)d_in[1];   // [H,E]  fp32
    const float* b = (const float*)d_in[2];   // [E]    fp32
    float* out = (float*)d_out;

    gemm_softmax_kernel<<<GEMM_BLOCKS, 128>>>(x, W, b, (char*)out);
    topk_kernel<<<G_N * E_N, 256>>>(out);
}

// round 11
// speedup vs baseline: 1.0615x; 1.0615x over previous
#include <cuda_runtime.h>
#include <cuda_bf16.h>
#include <float.h>
#include <stdint.h>

#define G_N 8
#define T_N 4096
#define H_N 1024
#define E_N 32
#define C_N 64
#define ROWS (G_N*T_N)                      // 32768
#define BR 64                               // rows per gemm block
#define GEMM_BLOCKS (ROWS/BR)               // 512
static const size_t NTOT = (size_t)G_N*T_N*E_N*C_N;   // 67108864

#define ZB_BYTES 32768                      // gemm bulk zero chunk (x32 = 1MiB/block)

// ---------------- scratch (no allocs allowed) ----------------
__device__ float g_probsT[E_N*ROWS];        // 4 MB: probs transposed [g][e][t]
__device__ float g_zpart[GEMM_BLOCKS];

// ---------------- packed fp32x2 helpers (asm: immune to fast-math) -----------
__device__ __forceinline__ unsigned long long ffma2(unsigned long long a,
                                                    unsigned long long b,
                                                    unsigned long long c) {
    unsigned long long d;
    asm("fma.rn.f32x2 %0, %1, %2, %3;" : "=l"(d) : "l"(a), "l"(b), "l"(c));
    return d;
}
__device__ __forceinline__ unsigned long long fadd2(unsigned long long a,
                                                    unsigned long long b) {
    unsigned long long d;
    asm("add.rn.f32x2 %0, %1, %2;" : "=l"(d) : "l"(a), "l"(b));
    return d;
}
__device__ __forceinline__ unsigned long long fneg2(unsigned long long a) {
    return a ^ 0x8000000080000000ull;
}
__device__ __forceinline__ unsigned long long splat2(float x) {
    unsigned long long d; unsigned int xi = __float_as_uint(x);
    asm("mov.b64 %0, {%1, %1};" : "=l"(d) : "r"(xi));
    return d;
}
__device__ __forceinline__ uint32_t smem_u32(const void* p) {
    uint32_t a;
    asm("{ .reg .u64 t; cvta.to.shared.u64 t, %1; cvt.u32.u64 %0, t; }"
        : "=r"(a) : "l"(p));
    return a;
}

// Accurate expf (<1 ulp) built from __fmaf_rn only (fast-math-proof).
__device__ __forceinline__ float exp_rn(float x) {
    float t = __fmaf_rn(x, 1.4426950408889634f, 12582912.0f);
    float n = __fadd_rn(t, -12582912.0f);
    float f = __fmaf_rn(n, -0.693359375f, x);
    f = __fmaf_rn(n, 2.1219444005469058e-4f, f);
    float p = 1.9841269841e-4f;
    p = __fmaf_rn(p, f, 1.3888888889e-3f);
    p = __fmaf_rn(p, f, 8.3333333333e-3f);
    p = __fmaf_rn(p, f, 4.1666666667e-2f);
    p = __fmaf_rn(p, f, 1.6666666667e-1f);
    p = __fmaf_rn(p, f, 0.5f);
    p = __fmaf_rn(p, f, 1.0f);
    p = __fmaf_rn(p, f, 1.0f);
    int ei = (int)n;
    float sc = __int_as_float((ei + 127) << 23);
    return p * sc;
}

// ---------------- GEMM + softmax + z-loss + TMA-bulk output zeroing ----------
// (Round-8 proven config: full 512 MiB zero-fill, 32 x 32KB bulk per block.)
#define KT 32
#define XS 36   // shx row stride (pad): conflict-free broadcast reads
__global__ __launch_bounds__(128) void gemm_softmax_kernel(
    const float* __restrict__ x, const float* __restrict__ W,
    const float* __restrict__ bias, char* __restrict__ zout)
{
    __shared__ __align__(16) float shx[BR * XS];        // 9.2 KB
    __shared__ __align__(16) float shw[KT * E_N];       // 4 KB
    __shared__ __align__(16) float4 zbuf[ZB_BYTES/16];  // 32 KB of zeros
    __shared__ float shz[4];

    int tid  = threadIdx.x;
    int row0 = blockIdx.x * BR;
    int eq   = tid & 3;
    int rg   = tid >> 2;        // 0..31
    int e0   = eq * 8;

    // zero the TMA source buffer (16 float4 per thread)
    const float4 zf4 = make_float4(0.f, 0.f, 0.f, 0.f);
    #pragma unroll
    for (int i = 0; i < 16; i++) zbuf[i * 128 + tid] = zf4;

    unsigned long long ksum[2][4], kcmp[2][4];
    #pragma unroll
    for (int r = 0; r < 2; r++)
        #pragma unroll
        for (int j = 0; j < 4; j++) { ksum[r][j] = 0ull; kcmp[r][j] = 0ull; }

    // prefetch registers
    float4 px[4], pw[2];
    #pragma unroll
    for (int i = 0; i < 4; i++) {
        int j = i * 128 + tid;
        px[i] = *(const float4*)(x + (size_t)(row0 + (j >> 3)) * H_N + (j & 7) * 4);
    }
    #pragma unroll
    for (int i = 0; i < 2; i++) {
        int j = i * 128 + tid;
        pw[i] = *(const float4*)(W + (size_t)(j >> 3) * E_N + (j & 7) * 4);
    }

    uint32_t zb_s = smem_u32(zbuf);

    for (int kt = 0; kt < H_N; kt += KT) {
        #pragma unroll
        for (int i = 0; i < 4; i++) {
            int j = i * 128 + tid;
            *(float4*)&shx[(j >> 3) * XS + (j & 7) * 4] = px[i];
        }
        #pragma unroll
        for (int i = 0; i < 2; i++) {
            int j = i * 128 + tid;
            *(float4*)&shw[(j >> 3) * E_N + (j & 7) * 4] = pw[i];
        }
        __syncthreads();   // also publishes zbuf zeros (iter 0)

        // one 32KB async bulk zero-store per chunk (elected thread)
        if (tid == 0) {
            if (kt == 0)
                asm volatile("fence.proxy.async.shared::cta;" ::: "memory");
            char* dst = zout + ((size_t)blockIdx.x * 32 + (size_t)(kt >> 5)) * ZB_BYTES;
            asm volatile(
                "cp.async.bulk.global.shared::cta.bulk_group [%0], [%1], %2;"
                :: "l"(dst), "r"(zb_s), "r"((unsigned)ZB_BYTES) : "memory");
        }

        int ktn = (kt + KT < H_N) ? kt + KT : 0;
        #pragma unroll
        for (int i = 0; i < 4; i++) {
            int j = i * 128 + tid;
            px[i] = *(const float4*)(x + (size_t)(row0 + (j >> 3)) * H_N + ktn + (j & 7) * 4);
        }
        #pragma unroll
        for (int i = 0; i < 2; i++) {
            int j = i * 128 + tid;
            pw[i] = *(const float4*)(W + (size_t)(ktn + (j >> 3)) * E_N + (j & 7) * 4);
        }

        unsigned long long a[2][4];
        #pragma unroll
        for (int r = 0; r < 2; r++)
            #pragma unroll
            for (int j = 0; j < 4; j++) a[r][j] = 0ull;

        #pragma unroll 8
        for (int kk = 0; kk < KT; kk++) {
            unsigned long long x0 = splat2(shx[rg * XS + kk]);
            unsigned long long x1 = splat2(shx[(rg + 32) * XS + kk]);
            ulonglong2 w0 = *(const ulonglong2*)&shw[kk * E_N + e0];
            ulonglong2 w1 = *(const ulonglong2*)&shw[kk * E_N + e0 + 4];
            a[0][0] = ffma2(x0, w0.x, a[0][0]);
            a[0][1] = ffma2(x0, w0.y, a[0][1]);
            a[0][2] = ffma2(x0, w1.x, a[0][2]);
            a[0][3] = ffma2(x0, w1.y, a[0][3]);
            a[1][0] = ffma2(x1, w0.x, a[1][0]);
            a[1][1] = ffma2(x1, w0.y, a[1][1]);
            a[1][2] = ffma2(x1, w1.x, a[1][2]);
            a[1][3] = ffma2(x1, w1.y, a[1][3]);
        }
        #pragma unroll
        for (int r = 0; r < 2; r++)
            #pragma unroll
            for (int j = 0; j < 4; j++) {
                unsigned long long y = fadd2(a[r][j], fneg2(kcmp[r][j]));
                unsigned long long t = fadd2(ksum[r][j], y);
                kcmp[r][j] = fadd2(fadd2(t, fneg2(ksum[r][j])), fneg2(y));
                ksum[r][j] = t;
            }
        __syncthreads();
    }

    // epilogue: per row -> logits, softmax, transposed store, z partial
    float zacc = 0.0f;
    float bv[8];
    #pragma unroll
    for (int e = 0; e < 8; e++) bv[e] = bias[e0 + e];

    #pragma unroll
    for (int r = 0; r < 2; r++) {
        float l[8];
        #pragma unroll
        for (int j = 0; j < 4; j++) {
            unsigned long long v = fadd2(ksum[r][j], kcmp[r][j]);
            l[2*j]   = __uint_as_float((unsigned int)(v & 0xffffffffull));
            l[2*j+1] = __uint_as_float((unsigned int)(v >> 32));
        }
        #pragma unroll
        for (int e = 0; e < 8; e++) l[e] = __fadd_rn(l[e], bv[e]);

        float m = l[0];
        #pragma unroll
        for (int e = 1; e < 8; e++) m = fmaxf(m, l[e]);
        m = fmaxf(m, __shfl_xor_sync(0xffffffffu, m, 1));
        m = fmaxf(m, __shfl_xor_sync(0xffffffffu, m, 2));

        float p[8], s = 0.f;
        #pragma unroll
        for (int e = 0; e < 8; e++) { p[e] = exp_rn(__fadd_rn(l[e], -m)); s = __fadd_rn(s, p[e]); }
        s = __fadd_rn(s, __shfl_xor_sync(0xffffffffu, s, 1));
        s = __fadd_rn(s, __shfl_xor_sync(0xffffffffu, s, 2));

        int grow = row0 + rg + 32 * r;
        int g    = grow >> 12;
        int t    = grow & (T_N - 1);
        float* dst = g_probsT + ((size_t)g * E_N + e0) * T_N + t;
        #pragma unroll
        for (int e = 0; e < 8; e++)
            dst[(size_t)e * T_N] = __fdiv_rn(p[e], s);   // IEEE div

        float lz = m + logf(s);
        zacc = __fmaf_rn(lz, lz, zacc);
    }

    float v = (eq == 0) ? zacc : 0.0f;
    #pragma unroll
    for (int off = 16; off; off >>= 1)
        v += __shfl_xor_sync(0xffffffffu, v, off);
    if ((tid & 31) == 0) shz[tid >> 5] = v;
    __syncthreads();
    if (tid == 0) {
        float zs = 0.f;
        #pragma unroll
        for (int w = 0; w < 4; w++) zs += shz[w];
        g_zpart[blockIdx.x] = zs;
        asm volatile("cp.async.bulk.commit_group;" ::: "memory");
        asm volatile("cp.async.bulk.wait_group 0;" ::: "memory");
    }
}

// ------- per-(g,e) exact top-64 via radix select + fused scatter -------------
// Warp-privatized histograms (8 copies) kill cross-warp same-bin atomic
// serialization; shuffle-based block scans. Selection = jax.lax.top_k
// semantics (value desc, index asc tie-break). Winners stored directly into
// the pre-zeroed outputs (ordering via stream: gemm drained all zeros).
__global__ __launch_bounds__(256) void topk_kernel(float* __restrict__ out)
{
    __shared__ unsigned int ub[T_N];         // 16 KB
    __shared__ int hist8[8][256];            // 8 KB: per-warp histograms
    __shared__ int wtot[8], wext[8];
    __shared__ int sel_bin, sel_krem;
    __shared__ unsigned long long glist[C_N];
    __shared__ int gcnt;
    __shared__ float red[8];

    int bid  = blockIdx.x;           // 0..255 = g*32 + e
    int g    = bid >> 5;
    int e    = bid & 31;
    int tid  = threadIdx.x;
    int lane = tid & 31;
    int wid  = tid >> 5;

    // load prob bits (order-preserving for positive floats)
    const float4* base = (const float4*)(g_probsT + (size_t)bid * T_N);
    #pragma unroll
    for (int i = 0; i < 4; i++) {
        float4 v = base[tid * 4 + i];
        uint4 u;
        u.x = __float_as_uint(v.x); u.y = __float_as_uint(v.y);
        u.z = __float_as_uint(v.z); u.w = __float_as_uint(v.w);
        *(uint4*)&ub[tid * 16 + i * 4] = u;
    }
    if (tid == 0) gcnt = 0;

    // ---- 4-level radix select ----
    unsigned int pref = 0;
    int k_rem = C_N;
    for (int lvl = 0; lvl < 4; lvl++) {
        int sh = 24 - 8 * lvl;
        // zero the 8 histogram copies (8 ints per thread)
        int* h8 = &hist8[0][0];
        #pragma unroll
        for (int i = 0; i < 8; i++) h8[i * 256 + tid] = 0;
        __syncthreads();
        #pragma unroll
        for (int i = 0; i < 16; i++) {
            unsigned int b = ub[tid * 16 + i];
            bool cand = (lvl == 0) || ((b >> (32 - 8 * lvl)) == pref);
            if (cand) atomicAdd(&hist8[wid][(b >> sh) & 255], 1);
        }
        __syncthreads();
        // fold copies: bin count for bin 'tid'
        int cnt = 0;
        #pragma unroll
        for (int w = 0; w < 8; w++) cnt += hist8[w][tid];
        // block suffix-inclusive scan via warp shfl + 8-warp combine
        int v = cnt;
        #pragma unroll
        for (int off = 1; off < 32; off <<= 1) {
            int t = __shfl_down_sync(0xffffffffu, v, off);
            if (lane + off < 32) v += t;
        }
        if (lane == 0) wtot[wid] = v;
        __syncthreads();
        if (tid < 8) {
            int s = 0;
            for (int w = tid + 1; w < 8; w++) s += wtot[w];
            wext[tid] = s;
        }
        __syncthreads();
        int S = v + wext[wid];                    // suffix for bin at my lane base..
        // v holds suffix within warp starting at my lane; need per-lane value:
        // recompute per-lane suffix from cnt (v was lane-local already)
        // NOTE: v above IS the lane-local suffix (shfl_down chain), so S is
        // the full suffix sum over bins >= tid.
        // find threshold bin: S >= k_rem and next-bin suffix < k_rem
        int Snext;
        {
            // suffix of bin tid+1 = S - cnt
            Snext = S - cnt;
        }
        if (S >= k_rem && Snext < k_rem) { sel_bin = tid; sel_krem = k_rem - Snext; }
        __syncthreads();
        pref  = (pref << 8) | (unsigned int)sel_bin;
        k_rem = sel_krem;
        __syncthreads();
    }
    unsigned int thr = pref;         // exact 64th-largest bit pattern
    int need   = k_rem;              // # equals to take (smallest indices)
    int cnt_gt = C_N - need;

    // compact strictly-greater winners (unordered) into smem
    #pragma unroll
    for (int i = 0; i < 16; i++) {
        int t = tid * 16 + i;
        unsigned int b = ub[t];
        if (b > thr) {
            int p = atomicAdd(&gcnt, 1);
            glist[p] = ((unsigned long long)b << 32) |
                       (unsigned long long)(0xFFFFFFFFu - (unsigned int)t);
        }
    }

    // equals: block prefix scan (ascending t) via warp shfl + combine
    int leq = 0;
    #pragma unroll
    for (int i = 0; i < 16; i++) leq += (ub[tid * 16 + i] == thr);
    int pv = leq;
    #pragma unroll
    for (int off = 1; off < 32; off <<= 1) {
        int t = __shfl_up_sync(0xffffffffu, pv, off);
        if (lane >= off) pv += t;
    }
    if (lane == 31) wtot[wid] = pv;
    __syncthreads();
    if (tid < 8) {
        int s = 0;
        for (int w = 0; w < tid; w++) s += wtot[w];
        wext[tid] = s;
    }
    __syncthreads();
    int ir0 = pv - leq + wext[wid];   // exclusive prefix of equal-counts
    __syncthreads();                  // glist/gcnt final

    // ---- winner stores (combine + dispatch) ----
    const size_t ge_off = ((size_t)g * T_N) * (E_N * C_N) + (size_t)e * C_N;

    {   // equals at threshold: ranks cnt_gt + index-rank
        int ir = ir0;
        #pragma unroll
        for (int i = 0; i < 16; i++) {
            int t = tid * 16 + i;
            if (ub[t] == thr) {
                if (ir < need) {
                    size_t off = ge_off + (size_t)t * (E_N * C_N) + (cnt_gt + ir);
                    out[off]        = __uint_as_float(thr);
                    out[NTOT + off] = 1.0f;
                }
                ir++;
            }
        }
    }
    if (tid < cnt_gt) {   // strictly greater: rank by composite key
        unsigned long long mk = glist[tid];
        int rank = 0;
        for (int j = 0; j < cnt_gt; j++) rank += (glist[j] > mk);
        int t = (int)(0xFFFFFFFFu - (unsigned int)(mk & 0xFFFFFFFFull));
        size_t off = ge_off + (size_t)t * (E_N * C_N) + rank;
        out[off]        = __uint_as_float((unsigned int)(mk >> 32));
        out[NTOT + off] = 1.0f;
    }

    // z-loss (block 0)
    if (bid == 0) {
        float v = 0.0f;
        for (int j = tid; j < GEMM_BLOCKS; j += 256) v += g_zpart[j];
        #pragma unroll
        for (int off = 16; off; off >>= 1)
            v += __shfl_xor_sync(0xffffffffu, v, off);
        if ((tid & 31) == 0) red[tid >> 5] = v;
        __syncthreads();
        if (tid == 0) {
            float zs = 0.f;
            #pragma unroll
            for (int w = 0; w < 8; w++) zs += red[w];
            out[2 * NTOT] = zs * (1.0f / (float)(G_N * T_N));
        }
    }
}

// ---------------- launch ----------------
extern "C" void kernel_launch(void* const* d_in, const int* in_sizes, int n_in,
                              void* d_out, int out_size)
{
    const float* x = (const float*)d_in[0];   // [G,T,H] fp32
    const float* W = (const float*)d_in[1];   // [H,E]  fp32
    const float* b = (const float*)d_in[2];   // [E]    fp32
    float* out = (float*)d_out;

    gemm_softmax_kernel<<<GEMM_BLOCKS, 128>>>(x, W, b, (char*)out);
    topk_kernel<<<G_N * E_N, 256>>>(out);
}

// round 13
// speedup vs baseline: 1.1307x; 1.0652x over previous
#include <cuda_runtime.h>
#include <cuda_bf16.h>
#include <float.h>
#include <stdint.h>

#define G_N 8
#define T_N 4096
#define H_N 1024
#define E_N 32
#define C_N 64
#define ROWS (G_N*T_N)                      // 32768
#define BR 64                               // rows per gemm block
#define GEMM_BLOCKS (ROWS/BR)               // 512
static const size_t NTOT = (size_t)G_N*T_N*E_N*C_N;   // 67108864

#define ZB_BYTES 32768                      // gemm bulk zero chunk (x32 = 1MiB/block)

// ---------------- scratch (no allocs allowed) ----------------
__device__ float g_probsT[E_N*ROWS];        // 4 MB: probs transposed [g][e][t]
__device__ float g_zpart[GEMM_BLOCKS];

// ---------------- packed fp32x2 helpers (asm: immune to fast-math) -----------
__device__ __forceinline__ unsigned long long ffma2(unsigned long long a,
                                                    unsigned long long b,
                                                    unsigned long long c) {
    unsigned long long d;
    asm("fma.rn.f32x2 %0, %1, %2, %3;" : "=l"(d) : "l"(a), "l"(b), "l"(c));
    return d;
}
__device__ __forceinline__ unsigned long long fadd2(unsigned long long a,
                                                    unsigned long long b) {
    unsigned long long d;
    asm("add.rn.f32x2 %0, %1, %2;" : "=l"(d) : "l"(a), "l"(b));
    return d;
}
__device__ __forceinline__ unsigned long long fneg2(unsigned long long a) {
    return a ^ 0x8000000080000000ull;
}
__device__ __forceinline__ unsigned long long splat2(float x) {
    unsigned long long d; unsigned int xi = __float_as_uint(x);
    asm("mov.b64 %0, {%1, %1};" : "=l"(d) : "r"(xi));
    return d;
}
__device__ __forceinline__ uint32_t smem_u32(const void* p) {
    uint32_t a;
    asm("{ .reg .u64 t; cvta.to.shared.u64 t, %1; cvt.u32.u64 %0, t; }"
        : "=r"(a) : "l"(p));
    return a;
}

// Accurate expf (<1 ulp) built from __fmaf_rn only (fast-math-proof).
__device__ __forceinline__ float exp_rn(float x) {
    float t = __fmaf_rn(x, 1.4426950408889634f, 12582912.0f);
    float n = __fadd_rn(t, -12582912.0f);
    float f = __fmaf_rn(n, -0.693359375f, x);
    f = __fmaf_rn(n, 2.1219444005469058e-4f, f);
    float p = 1.9841269841e-4f;
    p = __fmaf_rn(p, f, 1.3888888889e-3f);
    p = __fmaf_rn(p, f, 8.3333333333e-3f);
    p = __fmaf_rn(p, f, 4.1666666667e-2f);
    p = __fmaf_rn(p, f, 1.6666666667e-1f);
    p = __fmaf_rn(p, f, 0.5f);
    p = __fmaf_rn(p, f, 1.0f);
    p = __fmaf_rn(p, f, 1.0f);
    int ei = (int)n;
    float sc = __int_as_float((ei + 127) << 23);
    return p * sc;
}

// ---------------- GEMM + softmax + z-loss + TMA-bulk output zeroing ----------
// (Round-8 proven config: full 512 MiB zero-fill, 32 x 32KB bulk per block.)
#define KT 32
#define XS 36   // shx row stride (pad): conflict-free broadcast reads
__global__ __launch_bounds__(128) void gemm_softmax_kernel(
    const float* __restrict__ x, const float* __restrict__ W,
    const float* __restrict__ bias, char* __restrict__ zout)
{
    __shared__ __align__(16) float shx[BR * XS];        // 9.2 KB
    __shared__ __align__(16) float shw[KT * E_N];       // 4 KB
    __shared__ __align__(16) float4 zbuf[ZB_BYTES/16];  // 32 KB of zeros
    __shared__ float shz[4];

    int tid  = threadIdx.x;
    int row0 = blockIdx.x * BR;
    int eq   = tid & 3;
    int rg   = tid >> 2;        // 0..31
    int e0   = eq * 8;

    // zero the TMA source buffer (16 float4 per thread)
    const float4 zf4 = make_float4(0.f, 0.f, 0.f, 0.f);
    #pragma unroll
    for (int i = 0; i < 16; i++) zbuf[i * 128 + tid] = zf4;

    unsigned long long ksum[2][4], kcmp[2][4];
    #pragma unroll
    for (int r = 0; r < 2; r++)
        #pragma unroll
        for (int j = 0; j < 4; j++) { ksum[r][j] = 0ull; kcmp[r][j] = 0ull; }

    // prefetch registers
    float4 px[4], pw[2];
    #pragma unroll
    for (int i = 0; i < 4; i++) {
        int j = i * 128 + tid;
        px[i] = *(const float4*)(x + (size_t)(row0 + (j >> 3)) * H_N + (j & 7) * 4);
    }
    #pragma unroll
    for (int i = 0; i < 2; i++) {
        int j = i * 128 + tid;
        pw[i] = *(const float4*)(W + (size_t)(j >> 3) * E_N + (j & 7) * 4);
    }

    uint32_t zb_s = smem_u32(zbuf);

    for (int kt = 0; kt < H_N; kt += KT) {
        #pragma unroll
        for (int i = 0; i < 4; i++) {
            int j = i * 128 + tid;
            *(float4*)&shx[(j >> 3) * XS + (j & 7) * 4] = px[i];
        }
        #pragma unroll
        for (int i = 0; i < 2; i++) {
            int j = i * 128 + tid;
            *(float4*)&shw[(j >> 3) * E_N + (j & 7) * 4] = pw[i];
        }
        __syncthreads();   // also publishes zbuf zeros (iter 0)

        // one 32KB async bulk zero-store per chunk (elected thread)
        if (tid == 0) {
            if (kt == 0)
                asm volatile("fence.proxy.async.shared::cta;" ::: "memory");
            char* dst = zout + ((size_t)blockIdx.x * 32 + (size_t)(kt >> 5)) * ZB_BYTES;
            asm volatile(
                "cp.async.bulk.global.shared::cta.bulk_group [%0], [%1], %2;"
                :: "l"(dst), "r"(zb_s), "r"((unsigned)ZB_BYTES) : "memory");
        }

        int ktn = (kt + KT < H_N) ? kt + KT : 0;
        #pragma unroll
        for (int i = 0; i < 4; i++) {
            int j = i * 128 + tid;
            px[i] = *(const float4*)(x + (size_t)(row0 + (j >> 3)) * H_N + ktn + (j & 7) * 4);
        }
        #pragma unroll
        for (int i = 0; i < 2; i++) {
            int j = i * 128 + tid;
            pw[i] = *(const float4*)(W + (size_t)(ktn + (j >> 3)) * E_N + (j & 7) * 4);
        }

        unsigned long long a[2][4];
        #pragma unroll
        for (int r = 0; r < 2; r++)
            #pragma unroll
            for (int j = 0; j < 4; j++) a[r][j] = 0ull;

        #pragma unroll 8
        for (int kk = 0; kk < KT; kk++) {
            unsigned long long x0 = splat2(shx[rg * XS + kk]);
            unsigned long long x1 = splat2(shx[(rg + 32) * XS + kk]);
            ulonglong2 w0 = *(const ulonglong2*)&shw[kk * E_N + e0];
            ulonglong2 w1 = *(const ulonglong2*)&shw[kk * E_N + e0 + 4];
            a[0][0] = ffma2(x0, w0.x, a[0][0]);
            a[0][1] = ffma2(x0, w0.y, a[0][1]);
            a[0][2] = ffma2(x0, w1.x, a[0][2]);
            a[0][3] = ffma2(x0, w1.y, a[0][3]);
            a[1][0] = ffma2(x1, w0.x, a[1][0]);
            a[1][1] = ffma2(x1, w0.y, a[1][1]);
            a[1][2] = ffma2(x1, w1.x, a[1][2]);
            a[1][3] = ffma2(x1, w1.y, a[1][3]);
        }
        #pragma unroll
        for (int r = 0; r < 2; r++)
            #pragma unroll
            for (int j = 0; j < 4; j++) {
                unsigned long long y = fadd2(a[r][j], fneg2(kcmp[r][j]));
                unsigned long long t = fadd2(ksum[r][j], y);
                kcmp[r][j] = fadd2(fadd2(t, fneg2(ksum[r][j])), fneg2(y));
                ksum[r][j] = t;
            }
        __syncthreads();
    }

    // epilogue: per row -> logits, softmax, transposed store, z partial
    float zacc = 0.0f;
    float bv[8];
    #pragma unroll
    for (int e = 0; e < 8; e++) bv[e] = bias[e0 + e];

    #pragma unroll
    for (int r = 0; r < 2; r++) {
        float l[8];
        #pragma unroll
        for (int j = 0; j < 4; j++) {
            unsigned long long v = fadd2(ksum[r][j], kcmp[r][j]);
            l[2*j]   = __uint_as_float((unsigned int)(v & 0xffffffffull));
            l[2*j+1] = __uint_as_float((unsigned int)(v >> 32));
        }
        #pragma unroll
        for (int e = 0; e < 8; e++) l[e] = __fadd_rn(l[e], bv[e]);

        float m = l[0];
        #pragma unroll
        for (int e = 1; e < 8; e++) m = fmaxf(m, l[e]);
        m = fmaxf(m, __shfl_xor_sync(0xffffffffu, m, 1));
        m = fmaxf(m, __shfl_xor_sync(0xffffffffu, m, 2));

        float p[8], s = 0.f;
        #pragma unroll
        for (int e = 0; e < 8; e++) { p[e] = exp_rn(__fadd_rn(l[e], -m)); s = __fadd_rn(s, p[e]); }
        s = __fadd_rn(s, __shfl_xor_sync(0xffffffffu, s, 1));
        s = __fadd_rn(s, __shfl_xor_sync(0xffffffffu, s, 2));

        int grow = row0 + rg + 32 * r;
        int g    = grow >> 12;
        int t    = grow & (T_N - 1);
        float* dst = g_probsT + ((size_t)g * E_N + e0) * T_N + t;
        #pragma unroll
        for (int e = 0; e < 8; e++)
            dst[(size_t)e * T_N] = __fdiv_rn(p[e], s);   // IEEE div

        float lz = m + logf(s);
        zacc = __fmaf_rn(lz, lz, zacc);
    }

    float v = (eq == 0) ? zacc : 0.0f;
    #pragma unroll
    for (int off = 16; off; off >>= 1)
        v += __shfl_xor_sync(0xffffffffu, v, off);
    if ((tid & 31) == 0) shz[tid >> 5] = v;
    __syncthreads();
    if (tid == 0) {
        float zs = 0.f;
        #pragma unroll
        for (int w = 0; w < 4; w++) zs += shz[w];
        g_zpart[blockIdx.x] = zs;
        asm volatile("cp.async.bulk.commit_group;" ::: "memory");
        asm volatile("cp.async.bulk.wait_group 0;" ::: "memory");
    }
}

// ------- per-(g,e) exact top-64 via radix select + fused scatter -------------
// REGISTER-RESIDENT candidates: each thread keeps its 16 prob-bit values in
// registers (no ub[] smem array -> no 16-way-conflicted LDS re-reads per
// level). 8 warp-private histograms; shuffle-based block scans. Selection =
// jax.lax.top_k semantics (value desc, index asc tie-break). Winners stored
// into the pre-zeroed outputs (stream order: gemm drained all zeros).
__global__ __launch_bounds__(256) void topk_kernel(float* __restrict__ out)
{
    __shared__ int hist8[8][256];            // 8 KB: per-warp histograms
    __shared__ int wtot[8], wext[8];
    __shared__ int sel_bin, sel_krem;
    __shared__ unsigned long long glist[C_N];
    __shared__ int gcnt;
    __shared__ float red[8];

    int bid  = blockIdx.x;           // 0..255 = g*32 + e
    int g    = bid >> 5;
    int e    = bid & 31;
    int tid  = threadIdx.x;
    int lane = tid & 31;
    int wid  = tid >> 5;

    // load prob bits into REGISTERS (order-preserving for positive floats)
    unsigned int r[16];
    {
        const uint4* base = (const uint4*)(g_probsT + (size_t)bid * T_N);
        #pragma unroll
        for (int i = 0; i < 4; i++) {
            uint4 u = base[tid * 4 + i];
            r[i*4+0] = u.x; r[i*4+1] = u.y; r[i*4+2] = u.z; r[i*4+3] = u.w;
        }
    }
    if (tid == 0) gcnt = 0;

    // ---- 4-level radix select ----
    unsigned int pref = 0;
    int k_rem = C_N;
    for (int lvl = 0; lvl < 4; lvl++) {
        int sh = 24 - 8 * lvl;
        // zero the 8 histogram copies (2 uint4 per thread)
        {
            uint4* h4 = (uint4*)&hist8[0][0];
            const uint4 z4 = make_uint4(0u, 0u, 0u, 0u);
            h4[tid] = z4;
            h4[256 + tid] = z4;
        }
        __syncthreads();
        #pragma unroll
        for (int i = 0; i < 16; i++) {
            unsigned int b = r[i];
            bool cand = (lvl == 0) || ((b >> (32 - 8 * lvl)) == pref);
            if (cand) atomicAdd(&hist8[wid][(b >> sh) & 255], 1);
        }
        __syncthreads();
        // fold copies: count for bin 'tid'
        int cnt = 0;
        #pragma unroll
        for (int w = 0; w < 8; w++) cnt += hist8[w][tid];
        // block suffix-inclusive scan via warp shfl + 8-warp combine
        int v = cnt;
        #pragma unroll
        for (int off = 1; off < 32; off <<= 1) {
            int t = __shfl_down_sync(0xffffffffu, v, off);
            if (lane + off < 32) v += t;
        }
        if (lane == 0) wtot[wid] = v;
        __syncthreads();
        if (tid < 8) {
            int s = 0;
            for (int w = tid + 1; w < 8; w++) s += wtot[w];
            wext[tid] = s;
        }
        __syncthreads();
        int S = v + wext[wid];        // suffix sum over all bins >= tid
        int Snext = S - cnt;          // suffix of bin tid+1
        if (S >= k_rem && Snext < k_rem) { sel_bin = tid; sel_krem = k_rem - Snext; }
        __syncthreads();
        pref  = (pref << 8) | (unsigned int)sel_bin;
        k_rem = sel_krem;
        __syncthreads();
    }
    unsigned int thr = pref;         // exact 64th-largest bit pattern
    int need   = k_rem;              // # equals to take (smallest indices)
    int cnt_gt = C_N - need;

    // compact strictly-greater winners (unordered) into smem
    #pragma unroll
    for (int i = 0; i < 16; i++) {
        unsigned int b = r[i];
        if (b > thr) {
            int t = tid * 16 + i;
            int p = atomicAdd(&gcnt, 1);
            glist[p] = ((unsigned long long)b << 32) |
                       (unsigned long long)(0xFFFFFFFFu - (unsigned int)t);
        }
    }

    // equals: block prefix scan (ascending t) via warp shfl + combine
    int leq = 0;
    #pragma unroll
    for (int i = 0; i < 16; i++) leq += (r[i] == thr);
    int pv = leq;
    #pragma unroll
    for (int off = 1; off < 32; off <<= 1) {
        int t = __shfl_up_sync(0xffffffffu, pv, off);
        if (lane >= off) pv += t;
    }
    if (lane == 31) wtot[wid] = pv;
    __syncthreads();
    if (tid < 8) {
        int s = 0;
        for (int w = 0; w < tid; w++) s += wtot[w];
        wext[tid] = s;
    }
    __syncthreads();
    int ir0 = pv - leq + wext[wid];   // exclusive prefix of equal-counts
    __syncthreads();                  // glist/gcnt final

    // ---- winner stores (combine + dispatch) ----
    const size_t ge_off = ((size_t)g * T_N) * (E_N * C_N) + (size_t)e * C_N;

    {   // equals at threshold: ranks cnt_gt + index-rank
        int ir = ir0;
        #pragma unroll
        for (int i = 0; i < 16; i++) {
            if (r[i] == thr) {
                if (ir < need) {
                    int t = tid * 16 + i;
                    size_t off = ge_off + (size_t)t * (E_N * C_N) + (cnt_gt + ir);
                    out[off]        = __uint_as_float(thr);
                    out[NTOT + off] = 1.0f;
                }
                ir++;
            }
        }
    }
    if (tid < cnt_gt) {   // strictly greater: rank by composite key
        unsigned long long mk = glist[tid];
        int rank = 0;
        for (int j = 0; j < cnt_gt; j++) rank += (glist[j] > mk);
        int t = (int)(0xFFFFFFFFu - (unsigned int)(mk & 0xFFFFFFFFull));
        size_t off = ge_off + (size_t)t * (E_N * C_N) + rank;
        out[off]        = __uint_as_float((unsigned int)(mk >> 32));
        out[NTOT + off] = 1.0f;
    }

    // z-loss (block 0)
    if (bid == 0) {
        float v = 0.0f;
        for (int j = tid; j < GEMM_BLOCKS; j += 256) v += g_zpart[j];
        #pragma unroll
        for (int off = 16; off; off >>= 1)
            v += __shfl_xor_sync(0xffffffffu, v, off);
        if ((tid & 31) == 0) red[tid >> 5] = v;
        __syncthreads();
        if (tid == 0) {
            float zs = 0.f;
            #pragma unroll
            for (int w = 0; w < 8; w++) zs += red[w];
            out[2 * NTOT] = zs * (1.0f / (float)(G_N * T_N));
        }
    }
}

// ---------------- launch ----------------
extern "C" void kernel_launch(void* const* d_in, const int* in_sizes, int n_in,
                              void* d_out, int out_size)
{
    const float* x = (const float*)d_in[0];   // [G,T,H] fp32
    const float* W = (const float*)d_in[1];   // [H,E]  fp32
    const float* b = (const float*)d_in[2];   // [E]    fp32
    float* out = (float*)d_out;

    gemm_softmax_kernel<<<GEMM_BLOCKS, 128>>>(x, W, b, (char*)out);
    topk_kernel<<<G_N * E_N, 256>>>(out);
}

// round 16
// speedup vs baseline: 1.1443x; 1.0120x over previous
#include <cuda_runtime.h>
#include <cuda_bf16.h>
#include <float.h>
#include <stdint.h>

#define G_N 8
#define T_N 4096
#define H_N 1024
#define E_N 32
#define C_N 64
#define ROWS (G_N*T_N)                      // 32768
#define BR 64                               // rows per gemm block
#define GEMM_BLOCKS (ROWS/BR)               // 512
static const size_t NTOT = (size_t)G_N*T_N*E_N*C_N;   // 67108864

#define ZB_BYTES 32768                      // gemm bulk zero chunk (x32 = 1MiB/block)

// ---------------- scratch (no allocs allowed) ----------------
__device__ float g_probsT[E_N*ROWS];        // 4 MB: probs transposed [g][e][t]
__device__ float g_zpart[GEMM_BLOCKS];

// ---------------- packed fp32x2 helpers (asm: immune to fast-math) -----------
__device__ __forceinline__ unsigned long long ffma2(unsigned long long a,
                                                    unsigned long long b,
                                                    unsigned long long c) {
    unsigned long long d;
    asm("fma.rn.f32x2 %0, %1, %2, %3;" : "=l"(d) : "l"(a), "l"(b), "l"(c));
    return d;
}
__device__ __forceinline__ unsigned long long fadd2(unsigned long long a,
                                                    unsigned long long b) {
    unsigned long long d;
    asm("add.rn.f32x2 %0, %1, %2;" : "=l"(d) : "l"(a), "l"(b));
    return d;
}
__device__ __forceinline__ unsigned long long fneg2(unsigned long long a) {
    return a ^ 0x8000000080000000ull;
}
__device__ __forceinline__ unsigned long long splat2(float x) {
    unsigned long long d; unsigned int xi = __float_as_uint(x);
    asm("mov.b64 %0, {%1, %1};" : "=l"(d) : "r"(xi));
    return d;
}
__device__ __forceinline__ uint32_t smem_u32(const void* p) {
    uint32_t a;
    asm("{ .reg .u64 t; cvta.to.shared.u64 t, %1; cvt.u32.u64 %0, t; }"
        : "=r"(a) : "l"(p));
    return a;
}

// Accurate expf (<1 ulp) built from __fmaf_rn only (fast-math-proof).
__device__ __forceinline__ float exp_rn(float x) {
    float t = __fmaf_rn(x, 1.4426950408889634f, 12582912.0f);
    float n = __fadd_rn(t, -12582912.0f);
    float f = __fmaf_rn(n, -0.693359375f, x);
    f = __fmaf_rn(n, 2.1219444005469058e-4f, f);
    float p = 1.9841269841e-4f;
    p = __fmaf_rn(p, f, 1.3888888889e-3f);
    p = __fmaf_rn(p, f, 8.3333333333e-3f);
    p = __fmaf_rn(p, f, 4.1666666667e-2f);
    p = __fmaf_rn(p, f, 1.6666666667e-1f);
    p = __fmaf_rn(p, f, 0.5f);
    p = __fmaf_rn(p, f, 1.0f);
    p = __fmaf_rn(p, f, 1.0f);
    int ei = (int)n;
    float sc = __int_as_float((ei + 127) << 23);
    return p * sc;
}

// ---------------- GEMM + softmax + z-loss + TMA-bulk output zeroing ----------
// (Round-13 proven config, unchanged.)
#define KT 32
#define XS 36   // shx row stride (pad): conflict-free broadcast reads
__global__ __launch_bounds__(128) void gemm_softmax_kernel(
    const float* __restrict__ x, const float* __restrict__ W,
    const float* __restrict__ bias, char* __restrict__ zout)
{
    __shared__ __align__(16) float shx[BR * XS];        // 9.2 KB
    __shared__ __align__(16) float shw[KT * E_N];       // 4 KB
    __shared__ __align__(16) float4 zbuf[ZB_BYTES/16];  // 32 KB of zeros
    __shared__ float shz[4];

    int tid  = threadIdx.x;
    int row0 = blockIdx.x * BR;
    int eq   = tid & 3;
    int rg   = tid >> 2;        // 0..31
    int e0   = eq * 8;

    // zero the TMA source buffer (16 float4 per thread)
    const float4 zf4 = make_float4(0.f, 0.f, 0.f, 0.f);
    #pragma unroll
    for (int i = 0; i < 16; i++) zbuf[i * 128 + tid] = zf4;

    unsigned long long ksum[2][4], kcmp[2][4];
    #pragma unroll
    for (int r = 0; r < 2; r++)
        #pragma unroll
        for (int j = 0; j < 4; j++) { ksum[r][j] = 0ull; kcmp[r][j] = 0ull; }

    // prefetch registers
    float4 px[4], pw[2];
    #pragma unroll
    for (int i = 0; i < 4; i++) {
        int j = i * 128 + tid;
        px[i] = *(const float4*)(x + (size_t)(row0 + (j >> 3)) * H_N + (j & 7) * 4);
    }
    #pragma unroll
    for (int i = 0; i < 2; i++) {
        int j = i * 128 + tid;
        pw[i] = *(const float4*)(W + (size_t)(j >> 3) * E_N + (j & 7) * 4);
    }

    uint32_t zb_s = smem_u32(zbuf);

    for (int kt = 0; kt < H_N; kt += KT) {
        #pragma unroll
        for (int i = 0; i < 4; i++) {
            int j = i * 128 + tid;
            *(float4*)&shx[(j >> 3) * XS + (j & 7) * 4] = px[i];
        }
        #pragma unroll
        for (int i = 0; i < 2; i++) {
            int j = i * 128 + tid;
            *(float4*)&shw[(j >> 3) * E_N + (j & 7) * 4] = pw[i];
        }
        __syncthreads();   // also publishes zbuf zeros (iter 0)

        // one 32KB async bulk zero-store per chunk (elected thread)
        if (tid == 0) {
            if (kt == 0)
                asm volatile("fence.proxy.async.shared::cta;" ::: "memory");
            char* dst = zout + ((size_t)blockIdx.x * 32 + (size_t)(kt >> 5)) * ZB_BYTES;
            asm volatile(
                "cp.async.bulk.global.shared::cta.bulk_group [%0], [%1], %2;"
                :: "l"(dst), "r"(zb_s), "r"((unsigned)ZB_BYTES) : "memory");
        }

        int ktn = (kt + KT < H_N) ? kt + KT : 0;
        #pragma unroll
        for (int i = 0; i < 4; i++) {
            int j = i * 128 + tid;
            px[i] = *(const float4*)(x + (size_t)(row0 + (j >> 3)) * H_N + ktn + (j & 7) * 4);
        }
        #pragma unroll
        for (int i = 0; i < 2; i++) {
            int j = i * 128 + tid;
            pw[i] = *(const float4*)(W + (size_t)(ktn + (j >> 3)) * E_N + (j & 7) * 4);
        }

        unsigned long long a[2][4];
        #pragma unroll
        for (int r = 0; r < 2; r++)
            #pragma unroll
            for (int j = 0; j < 4; j++) a[r][j] = 0ull;

        #pragma unroll 8
        for (int kk = 0; kk < KT; kk++) {
            unsigned long long x0 = splat2(shx[rg * XS + kk]);
            unsigned long long x1 = splat2(shx[(rg + 32) * XS + kk]);
            ulonglong2 w0 = *(const ulonglong2*)&shw[kk * E_N + e0];
            ulonglong2 w1 = *(const ulonglong2*)&shw[kk * E_N + e0 + 4];
            a[0][0] = ffma2(x0, w0.x, a[0][0]);
            a[0][1] = ffma2(x0, w0.y, a[0][1]);
            a[0][2] = ffma2(x0, w1.x, a[0][2]);
            a[0][3] = ffma2(x0, w1.y, a[0][3]);
            a[1][0] = ffma2(x1, w0.x, a[1][0]);
            a[1][1] = ffma2(x1, w0.y, a[1][1]);
            a[1][2] = ffma2(x1, w1.x, a[1][2]);
            a[1][3] = ffma2(x1, w1.y, a[1][3]);
        }
        #pragma unroll
        for (int r = 0; r < 2; r++)
            #pragma unroll
            for (int j = 0; j < 4; j++) {
                unsigned long long y = fadd2(a[r][j], fneg2(kcmp[r][j]));
                unsigned long long t = fadd2(ksum[r][j], y);
                kcmp[r][j] = fadd2(fadd2(t, fneg2(ksum[r][j])), fneg2(y));
                ksum[r][j] = t;
            }
        __syncthreads();
    }

    // epilogue: per row -> logits, softmax, transposed store, z partial
    float zacc = 0.0f;
    float bv[8];
    #pragma unroll
    for (int e = 0; e < 8; e++) bv[e] = bias[e0 + e];

    #pragma unroll
    for (int r = 0; r < 2; r++) {
        float l[8];
        #pragma unroll
        for (int j = 0; j < 4; j++) {
            unsigned long long v = fadd2(ksum[r][j], kcmp[r][j]);
            l[2*j]   = __uint_as_float((unsigned int)(v & 0xffffffffull));
            l[2*j+1] = __uint_as_float((unsigned int)(v >> 32));
        }
        #pragma unroll
        for (int e = 0; e < 8; e++) l[e] = __fadd_rn(l[e], bv[e]);

        float m = l[0];
        #pragma unroll
        for (int e = 1; e < 8; e++) m = fmaxf(m, l[e]);
        m = fmaxf(m, __shfl_xor_sync(0xffffffffu, m, 1));
        m = fmaxf(m, __shfl_xor_sync(0xffffffffu, m, 2));

        float p[8], s = 0.f;
        #pragma unroll
        for (int e = 0; e < 8; e++) { p[e] = exp_rn(__fadd_rn(l[e], -m)); s = __fadd_rn(s, p[e]); }
        s = __fadd_rn(s, __shfl_xor_sync(0xffffffffu, s, 1));
        s = __fadd_rn(s, __shfl_xor_sync(0xffffffffu, s, 2));

        int grow = row0 + rg + 32 * r;
        int g    = grow >> 12;
        int t    = grow & (T_N - 1);
        float* dst = g_probsT + ((size_t)g * E_N + e0) * T_N + t;
        #pragma unroll
        for (int e = 0; e < 8; e++)
            dst[(size_t)e * T_N] = __fdiv_rn(p[e], s);   // IEEE div

        float lz = m + logf(s);
        zacc = __fmaf_rn(lz, lz, zacc);
    }

    float v = (eq == 0) ? zacc : 0.0f;
    #pragma unroll
    for (int off = 16; off; off >>= 1)
        v += __shfl_xor_sync(0xffffffffu, v, off);
    if ((tid & 31) == 0) shz[tid >> 5] = v;
    __syncthreads();
    if (tid == 0) {
        float zs = 0.f;
        #pragma unroll
        for (int w = 0; w < 4; w++) zs += shz[w];
        g_zpart[blockIdx.x] = zs;
        asm volatile("cp.async.bulk.commit_group;" ::: "memory");
        asm volatile("cp.async.bulk.wait_group 0;" ::: "memory");
    }
}

// ------- per-(g,e) exact top-64 via radix select + fused scatter -------------
// 512 threads/block (8 elems/thread), 16 warp-private histograms: halves the
// per-warp atomic chains and candidate loops vs the 256-thread version.
// Register-resident candidates; shuffle scans; jax.lax.top_k semantics
// (value desc, index asc tie-break). Stream order: gemm drained all zeros.
__global__ __launch_bounds__(512) void topk_kernel(float* __restrict__ out)
{
    __shared__ int hist16[16][256];          // 16 KB: per-warp histograms
    __shared__ int wtot[16], wext[16];
    __shared__ int sel_bin, sel_krem;
    __shared__ unsigned long long glist[C_N];
    __shared__ int gcnt;
    __shared__ float red[16];

    int bid  = blockIdx.x;           // 0..255 = g*32 + e
    int g    = bid >> 5;
    int e    = bid & 31;
    int tid  = threadIdx.x;
    int lane = tid & 31;
    int wid  = tid >> 5;             // 0..15

    // load prob bits into REGISTERS (order-preserving for positive floats)
    unsigned int r[8];
    {
        const uint4* base = (const uint4*)(g_probsT + (size_t)bid * T_N);
        #pragma unroll
        for (int i = 0; i < 2; i++) {
            uint4 u = base[tid * 2 + i];
            r[i*4+0] = u.x; r[i*4+1] = u.y; r[i*4+2] = u.z; r[i*4+3] = u.w;
        }
    }
    if (tid == 0) gcnt = 0;

    // ---- 4-level radix select ----
    unsigned int pref = 0;
    int k_rem = C_N;
    for (int lvl = 0; lvl < 4; lvl++) {
        int sh = 24 - 8 * lvl;
        // zero the 16 histogram copies (2 uint4 per thread)
        {
            uint4* h4 = (uint4*)&hist16[0][0];
            const uint4 z4 = make_uint4(0u, 0u, 0u, 0u);
            h4[tid] = z4;
            h4[512 + tid] = z4;
        }
        __syncthreads();
        #pragma unroll
        for (int i = 0; i < 8; i++) {
            unsigned int b = r[i];
            bool cand = (lvl == 0) || ((b >> (32 - 8 * lvl)) == pref);
            if (cand) atomicAdd(&hist16[wid][(b >> sh) & 255], 1);
        }
        __syncthreads();
        // first 256 threads: fold 16 copies, suffix-scan, find threshold bin
        int cnt = 0, v = 0;
        if (tid < 256) {
            #pragma unroll
            for (int w = 0; w < 16; w++) cnt += hist16[w][tid];
            v = cnt;
            #pragma unroll
            for (int off = 1; off < 32; off <<= 1) {
                int t = __shfl_down_sync(0xffffffffu, v, off);
                if (lane + off < 32) v += t;
            }
            if (lane == 0) wtot[tid >> 5] = v;
        }
        __syncthreads();
        if (tid < 8) {
            int s = 0;
            for (int w = tid + 1; w < 8; w++) s += wtot[w];
            wext[tid] = s;
        }
        __syncthreads();
        if (tid < 256) {
            int S = v + wext[tid >> 5];   // suffix sum over all bins >= tid
            int Snext = S - cnt;          // suffix of bin tid+1
            if (S >= k_rem && Snext < k_rem) { sel_bin = tid; sel_krem = k_rem - Snext; }
        }
        __syncthreads();
        pref  = (pref << 8) | (unsigned int)sel_bin;
        k_rem = sel_krem;
        __syncthreads();
    }
    unsigned int thr = pref;         // exact 64th-largest bit pattern
    int need   = k_rem;              // # equals to take (smallest indices)
    int cnt_gt = C_N - need;

    // compact strictly-greater winners (unordered) into smem
    #pragma unroll
    for (int i = 0; i < 8; i++) {
        unsigned int b = r[i];
        if (b > thr) {
            int t = tid * 8 + i;
            int p = atomicAdd(&gcnt, 1);
            glist[p] = ((unsigned long long)b << 32) |
                       (unsigned long long)(0xFFFFFFFFu - (unsigned int)t);
        }
    }

    // equals: block prefix scan (ascending t) via warp shfl + 16-warp combine
    int leq = 0;
    #pragma unroll
    for (int i = 0; i < 8; i++) leq += (r[i] == thr);
    int pv = leq;
    #pragma unroll
    for (int off = 1; off < 32; off <<= 1) {
        int t = __shfl_up_sync(0xffffffffu, pv, off);
        if (lane >= off) pv += t;
    }
    if (lane == 31) wtot[wid] = pv;
    __syncthreads();
    if (tid < 16) {
        int s = 0;
        for (int w = 0; w < tid; w++) s += wtot[w];
        wext[tid] = s;
    }
    __syncthreads();
    int ir0 = pv - leq + wext[wid];   // exclusive prefix of equal-counts
    __syncthreads();                  // glist/gcnt final

    // ---- winner stores (combine + dispatch) ----
    const size_t ge_off = ((size_t)g * T_N) * (E_N * C_N) + (size_t)e * C_N;

    {   // equals at threshold: ranks cnt_gt + index-rank
        int ir = ir0;
        #pragma unroll
        for (int i = 0; i < 8; i++) {
            if (r[i] == thr) {
                if (ir < need) {
                    int t = tid * 8 + i;
                    size_t off = ge_off + (size_t)t * (E_N * C_N) + (cnt_gt + ir);
                    out[off]        = __uint_as_float(thr);
                    out[NTOT + off] = 1.0f;
                }
                ir++;
            }
        }
    }
    if (tid < cnt_gt) {   // strictly greater: rank by composite key
        unsigned long long mk = glist[tid];
        int rank = 0;
        for (int j = 0; j < cnt_gt; j++) rank += (glist[j] > mk);
        int t = (int)(0xFFFFFFFFu - (unsigned int)(mk & 0xFFFFFFFFull));
        size_t off = ge_off + (size_t)t * (E_N * C_N) + rank;
        out[off]        = __uint_as_float((unsigned int)(mk >> 32));
        out[NTOT + off] = 1.0f;
    }

    // z-loss (block 0)
    if (bid == 0) {
        float v = g_zpart[tid];       // 512 threads == GEMM_BLOCKS entries
        #pragma unroll
        for (int off = 16; off; off >>= 1)
            v += __shfl_xor_sync(0xffffffffu, v, off);
        if (lane == 0) red[wid] = v;
        __syncthreads();
        if (tid == 0) {
            float zs = 0.f;
            #pragma unroll
            for (int w = 0; w < 16; w++) zs += red[w];
            out[2 * NTOT] = zs * (1.0f / (float)(G_N * T_N));
        }
    }
}

// ---------------- launch ----------------
extern "C" void kernel_launch(void* const* d_in, const int* in_sizes, int n_in,
                              void* d_out, int out_size)
{
    const float* x = (const float*)d_in[0];   // [G,T,H] fp32
    const float* W = (const float*)d_in[1];   // [H,E]  fp32
    const float* b = (const float*)d_in[2];   // [E]    fp32
    float* out = (float*)d_out;

    gemm_softmax_kernel<<<GEMM_BLOCKS, 128>>>(x, W, b, (char*)out);
    topk_kernel<<<G_N * E_N, 512>>>(out);
}